// round 16
// baseline (speedup 1.0000x reference)
#include <cuda_runtime.h>

#define B_TOTAL 32768
#define F_TOTAL 200
#define D_IN    5
#define H_DIM   15
#define OUT_DIM 30
#define OPAD    32
#define FSPLIT  25
#define FCHUNK  (F_TOTAL / FSPLIT)   // 8
#define FSUB    4                    // features per y sub-tile (80B rows, 16B aligned)
#define NSUB    (FCHUNK / FSUB)      // 2
#define TPB     128
#define ROWS_PER_CTA 256             // R=2 rows per thread
#define NBX     (B_TOTAL / ROWS_PER_CTA)   // 128
#define YCOLS   (FSUB * D_IN)        // 20 floats = 80 B
#define YSTRIDE 20                   // 20*lane mod 32 covers all banks -> LDS.128 conflict-free
#define YTILE   (ROWS_PER_CTA * YSTRIDE)   // 5120 floats per buffer
#define YROW    (F_TOTAL * D_IN)     // 1000

// smem layout (floats): W 1280 | B 256 | C 256 | 2x y-tile 5120 => 48128 B -> 4 CTAs/SM
#define SM_W 0
#define SM_B (FCHUNK * D_IN * OPAD)             // 1280
#define SM_C (SM_B + FCHUNK * OPAD)             // 1536
#define SM_Y (SM_C + FCHUNK * OPAD)             // 1792 (x4 = 7168 B, 16B aligned)
#define SM_TOTAL ((SM_Y + 2 * YTILE) * 4)

// Scratch (allocation-free rule: __device__ globals)
__device__ __align__(16) float g_W12[F_TOTAL * D_IN * OPAD];
__device__ __align__(16) float g_b12[F_TOTAL * OPAD];
__device__ __align__(16) float g_W3p[F_TOTAL * OPAD];
__device__ __align__(16) float g_partial[FSPLIT][B_TOTAL];
__device__ int g_count[NBX];

// ---- packed f32x2 helpers ----
static __device__ __forceinline__ unsigned long long pk2(float x, float y) {
    unsigned long long r;
    asm("mov.b64 %0, {%1, %2};" : "=l"(r)
        : "r"(__float_as_uint(x)), "r"(__float_as_uint(y)));
    return r;
}
static __device__ __forceinline__ void upk2(unsigned long long v, float& x, float& y) {
    unsigned a, b;
    asm("mov.b64 {%0, %1}, %2;" : "=r"(a), "=r"(b) : "l"(v));
    x = __uint_as_float(a); y = __uint_as_float(b);
}
static __device__ __forceinline__ unsigned long long ffma2(
    unsigned long long a, unsigned long long b, unsigned long long c) {
    unsigned long long d;
    asm("fma.rn.f32x2 %0, %1, %2, %3;" : "=l"(d) : "l"(a), "l"(b), "l"(c));
    return d;
}
static __device__ __forceinline__ unsigned long long relu2(unsigned long long v) {
    float a, b;
    upk2(v, a, b);
    return pk2(fmaxf(a, 0.f), fmaxf(b, 0.f));
}

// ---- cp.async helpers ----
static __device__ __forceinline__ void cp_async16(unsigned dst_smem, const float* src) {
    asm volatile("cp.async.cg.shared.global [%0], [%1], 16;"
                 :: "r"(dst_smem), "l"(src));
}

// 16B-chunk staging: 256 rows x 5 chunks, all lanes active, row-major chunk order
static __device__ __forceinline__ void stage_tile(unsigned dst_u32,
                                                  const float* __restrict__ src,
                                                  int tid) {
    #pragma unroll
    for (int it = 0; it < (ROWS_PER_CTA * 5) / TPB; ++it) {   // 10 iterations
        const int k = tid + it * TPB;
        const int r = k / 5;
        const int c = k - r * 5;
        cp_async16(dst_u32 + (unsigned)(r * YSTRIDE + c * 4) * 4u,
                   src + (size_t)r * YROW + c * 4);
    }
}

// ---- Kernel 1: fold W1@W2 (no ReLU between the two linears) + reset counters ----
__global__ void prep_kernel(const float* __restrict__ W1, const float* __restrict__ b1,
                            const float* __restrict__ W2, const float* __restrict__ b2,
                            const float* __restrict__ W3) {
    const int idx = blockIdx.x * blockDim.x + threadIdx.x;
    if (idx < NBX) g_count[idx] = 0;                    // arrival counters for main
    if (idx < F_TOTAL * D_IN * OPAD) {
        const int f = idx / (D_IN * OPAD);
        const int rem = idx - f * (D_IN * OPAD);
        const int i = rem >> 5, o = rem & 31;
        const float* w1 = W1 + (f * D_IN + i) * H_DIM;
        const float* w2 = W2 + f * H_DIM * OUT_DIM + o;
        float s = 0.f;
        if (o < OUT_DIM) {
            #pragma unroll
            for (int h = 0; h < H_DIM; ++h) s += w1[h] * w2[h * OUT_DIM];
        }
        g_W12[idx] = s;
    } else if (idx < F_TOTAL * D_IN * OPAD + F_TOTAL * OPAD) {
        const int k = idx - F_TOTAL * D_IN * OPAD;
        const int f = k >> 5, o = k & 31;
        float sb = 0.f, w3v = 0.f;
        if (o < OUT_DIM) {
            const float* w2 = W2 + f * H_DIM * OUT_DIM + o;
            #pragma unroll
            for (int h = 0; h < H_DIM; ++h) sb += b1[f * H_DIM + h] * w2[h * OUT_DIM];
            sb += b2[f * OUT_DIM + o];
            w3v = W3[f * OUT_DIM + o];
        }
        g_b12[k] = sb;
        g_W3p[k] = w3v;
    }
}

// ---- Kernel 2: main fused MLP (R11 config) + fused deterministic reduce ----
__global__ __launch_bounds__(TPB, 4) void main_kernel(const float* __restrict__ y,
                                                      float* __restrict__ out,
                                                      const float* __restrict__ b3) {
    extern __shared__ __align__(16) float smem[];
    float* sW = smem + SM_W;
    float* sB = smem + SM_B;
    float* sC = smem + SM_C;
    float* sY = smem + SM_Y;
    __shared__ int s_ticket;

    const int tid  = threadIdx.x;
    const int fsplit = blockIdx.y;
    const int fbase = fsplit * FCHUNK;
    const int bx = blockIdx.x;
    const int b0 = bx * ROWS_PER_CTA;

    const unsigned sY_u32 = (unsigned)__cvta_generic_to_shared(sY);
    const float* ybase = y + (size_t)b0 * YROW + fbase * D_IN;

    // prologue: stage BOTH sub-tiles (two commit groups), then weights
    stage_tile(sY_u32, ybase, tid);
    asm volatile("cp.async.commit_group;");
    stage_tile(sY_u32 + (unsigned)YTILE * 4u, ybase + FSUB * D_IN, tid);
    asm volatile("cp.async.commit_group;");

    {
        const float4* gw = (const float4*)(g_W12 + fbase * D_IN * OPAD);
        float4* sw4 = (float4*)sW;
        #pragma unroll
        for (int t = tid; t < FCHUNK * D_IN * OPAD / 4; t += TPB) sw4[t] = gw[t];
        if (tid < FCHUNK * OPAD / 4) {
            ((float4*)sB)[tid] = ((const float4*)(g_b12 + fbase * OPAD))[tid];
            ((float4*)sC)[tid] = ((const float4*)(g_W3p + fbase * OPAD))[tid];
        }
    }

    unsigned long long accA0 = 0ull, accB0 = 0ull;   // row b0+tid
    unsigned long long accA1 = 0ull, accB1 = 0ull;   // row b0+tid+TPB

    #pragma unroll
    for (int s = 0; s < NSUB; ++s) {
        if (s == 0) asm volatile("cp.async.wait_group 1;");
        else        asm volatile("cp.async.wait_group 0;");
        __syncthreads();

        // vector y loads: 5 conflict-free LDS.128 per row
        const float4* yb0 = (const float4*)(sY + s * YTILE + tid * YSTRIDE);
        const float4* yb1 = (const float4*)(sY + s * YTILE + (tid + TPB) * YSTRIDE);
        float r0f[YCOLS], r1f[YCOLS];
        #pragma unroll
        for (int j = 0; j < 5; ++j) {
            *(float4*)&r0f[j * 4] = yb0[j];
            *(float4*)&r1f[j * 4] = yb1[j];
        }

        #pragma unroll
        for (int ff = 0; ff < FSUB; ++ff) {
            const int f = s * FSUB + ff;
            unsigned long long yp0[D_IN], yp1[D_IN];
            #pragma unroll
            for (int i = 0; i < D_IN; ++i) {
                const float v0 = r0f[ff * D_IN + i];
                const float v1 = r1f[ff * D_IN + i];
                yp0[i] = pk2(v0, v0);
                yp1[i] = pk2(v1, v1);
            }
            const ulonglong2* wp = (const ulonglong2*)(sW + f * D_IN * OPAD);
            const ulonglong2* bp = (const ulonglong2*)(sB + f * OPAD);
            const ulonglong2* cp = (const ulonglong2*)(sC + f * OPAD);

            #pragma unroll
            for (int j = 0; j < OPAD / 4; ++j) {
                ulonglong2 bb = bp[j];
                ulonglong2 t0 = bb, t1 = bb;
                #pragma unroll
                for (int i = 0; i < D_IN; ++i) {
                    ulonglong2 w = wp[i * (OPAD / 4) + j];   // broadcast LDS.128
                    t0.x = ffma2(yp0[i], w.x, t0.x);
                    t0.y = ffma2(yp0[i], w.y, t0.y);
                    t1.x = ffma2(yp1[i], w.x, t1.x);
                    t1.y = ffma2(yp1[i], w.y, t1.y);
                }
                ulonglong2 c = cp[j];
                accA0 = ffma2(relu2(t0.x), c.x, accA0);
                accB0 = ffma2(relu2(t0.y), c.y, accB0);
                accA1 = ffma2(relu2(t1.x), c.x, accA1);
                accB1 = ffma2(relu2(t1.y), c.y, accB1);
            }
        }
    }

    {
        float r0, r1, r2, r3;
        upk2(accA0, r0, r1); upk2(accB0, r2, r3);
        g_partial[fsplit][b0 + tid] = (r0 + r1) + (r2 + r3);
        upk2(accA1, r0, r1); upk2(accB1, r2, r3);
        g_partial[fsplit][b0 + tid + TPB] = (r0 + r1) + (r2 + r3);
    }

    // ---- fused deterministic reduction: last CTA of this bx sums all partials ----
    __threadfence();                 // publish our partial stores
    __syncthreads();                 // all threads of this CTA have stored+fenced
    if (tid == 0) s_ticket = atomicAdd(&g_count[bx], 1);
    __syncthreads();
    if (s_ticket == FSPLIT - 1) {
        __threadfence();             // acquire: see all other CTAs' partials
        const float bias3 = b3[0];
        #pragma unroll
        for (int rr = 0; rr < 2; ++rr) {
            const int row = b0 + tid + rr * TPB;
            float s0 = 0.f, s1 = 0.f, s2 = 0.f, s3 = 0.f, s4 = 0.f;
            #pragma unroll
            for (int p = 0; p < 5; ++p) {       // fixed order -> deterministic
                s0 += g_partial[p][row];
                s1 += g_partial[5 + p][row];
                s2 += g_partial[10 + p][row];
                s3 += g_partial[15 + p][row];
                s4 += g_partial[20 + p][row];
            }
            out[row] = (((s0 + s1) + (s2 + s3)) + s4) + bias3;
        }
    }
}

extern "C" void kernel_launch(void* const* d_in, const int* in_sizes, int n_in,
                              void* d_out, int out_size) {
    const float* y  = (const float*)d_in[0];
    const float* W1 = (const float*)d_in[1];
    const float* b1 = (const float*)d_in[2];
    const float* W2 = (const float*)d_in[3];
    const float* b2 = (const float*)d_in[4];
    const float* W3 = (const float*)d_in[5];
    const float* b3 = (const float*)d_in[6];
    float* out = (float*)d_out;

    cudaFuncSetAttribute(main_kernel,
                         cudaFuncAttributeMaxDynamicSharedMemorySize, SM_TOTAL);

    {   // launch #1: fold weights + reset arrival counters
        const int total = F_TOTAL * D_IN * OPAD + F_TOTAL * OPAD;
        prep_kernel<<<(total + 255) / 256, 256>>>(W1, b1, W2, b2, W3);
    }

    // launch #2: main + fused reduce
    dim3 grid(NBX, FSPLIT);                      // 128 x 25 = 3200 CTAs
    main_kernel<<<grid, TPB, SM_TOTAL>>>(y, out, b3);
}

// round 17
// speedup vs baseline: 1.5101x; 1.5101x over previous
#include <cuda_runtime.h>

#define B_TOTAL 32768
#define F_TOTAL 200
#define D_IN    5
#define H_DIM   15
#define OUT_DIM 30
#define OPAD    32
#define FSPLIT  25
#define FCHUNK  (F_TOTAL / FSPLIT)   // 8
#define FSUB    4                    // features per y stage (80B rows, 16B aligned)
#define NSUB    (FCHUNK / FSUB)      // 2
#define TPB     128
#define ROWS_PER_CTA 256             // R=2 rows per thread
#define NBX     (B_TOTAL / ROWS_PER_CTA)   // 128
#define YCOLS   (FSUB * D_IN)        // 20 floats = 80 B
#define YSTRIDE 20                   // 20*lane mod 32 covers all banks -> LDS.128 conflict-free
#define YTILE   (ROWS_PER_CTA * YSTRIDE)   // 5120 floats (ONE buffer, reused)
#define YROW    (F_TOTAL * D_IN)     // 1000

// Scratch (allocation-free rule: __device__ globals)
__device__ __align__(16) float g_W12[F_TOTAL * D_IN * OPAD];
__device__ __align__(16) float g_b12[F_TOTAL * OPAD];
__device__ __align__(16) float g_W3p[F_TOTAL * OPAD];
__device__ __align__(16) float g_partial[FSPLIT][B_TOTAL];
__device__ int g_count[NBX];

// ---- packed f32x2 helpers ----
static __device__ __forceinline__ unsigned long long pk2(float x, float y) {
    unsigned long long r;
    asm("mov.b64 %0, {%1, %2};" : "=l"(r)
        : "r"(__float_as_uint(x)), "r"(__float_as_uint(y)));
    return r;
}
static __device__ __forceinline__ void upk2(unsigned long long v, float& x, float& y) {
    unsigned a, b;
    asm("mov.b64 {%0, %1}, %2;" : "=r"(a), "=r"(b) : "l"(v));
    x = __uint_as_float(a); y = __uint_as_float(b);
}
static __device__ __forceinline__ unsigned long long ffma2(
    unsigned long long a, unsigned long long b, unsigned long long c) {
    unsigned long long d;
    asm("fma.rn.f32x2 %0, %1, %2, %3;" : "=l"(d) : "l"(a), "l"(b), "l"(c));
    return d;
}
static __device__ __forceinline__ unsigned long long relu2(unsigned long long v) {
    float a, b;
    upk2(v, a, b);
    return pk2(fmaxf(a, 0.f), fmaxf(b, 0.f));
}

// ---- cp.async helpers ----
static __device__ __forceinline__ void cp_async16(unsigned dst_smem, const float* src) {
    asm volatile("cp.async.cg.shared.global [%0], [%1], 16;"
                 :: "r"(dst_smem), "l"(src));
}

// 16B-chunk staging: 256 rows x 5 chunks, all lanes active
static __device__ __forceinline__ void stage_tile(unsigned dst_u32,
                                                  const float* __restrict__ src,
                                                  int tid) {
    #pragma unroll
    for (int it = 0; it < (ROWS_PER_CTA * 5) / TPB; ++it) {   // 10 iterations
        const int k = tid + it * TPB;
        const int r = k / 5;
        const int c = k - r * 5;
        cp_async16(dst_u32 + (unsigned)(r * YSTRIDE + c * 4) * 4u,
                   src + (size_t)r * YROW + c * 4);
    }
}

// ---- Kernel 1: fold W1@W2 (no ReLU between the two linears) + reset counters ----
__global__ void prep_kernel(const float* __restrict__ W1, const float* __restrict__ b1,
                            const float* __restrict__ W2, const float* __restrict__ b2,
                            const float* __restrict__ W3) {
    const int idx = blockIdx.x * blockDim.x + threadIdx.x;
    if (idx < NBX) g_count[idx] = 0;                    // arrival counters for main
    if (idx < F_TOTAL * D_IN * OPAD) {
        const int f = idx / (D_IN * OPAD);
        const int rem = idx - f * (D_IN * OPAD);
        const int i = rem >> 5, o = rem & 31;
        const float* w1 = W1 + (f * D_IN + i) * H_DIM;
        const float* w2 = W2 + f * H_DIM * OUT_DIM + o;
        float s = 0.f;
        if (o < OUT_DIM) {
            #pragma unroll
            for (int h = 0; h < H_DIM; ++h) s += w1[h] * w2[h * OUT_DIM];
        }
        g_W12[idx] = s;
    } else if (idx < F_TOTAL * D_IN * OPAD + F_TOTAL * OPAD) {
        const int k = idx - F_TOTAL * D_IN * OPAD;
        const int f = k >> 5, o = k & 31;
        float sb = 0.f, w3v = 0.f;
        if (o < OUT_DIM) {
            const float* w2 = W2 + f * H_DIM * OUT_DIM + o;
            #pragma unroll
            for (int h = 0; h < H_DIM; ++h) sb += b1[f * H_DIM + h] * w2[h * OUT_DIM];
            sb += b2[f * OUT_DIM + o];
            w3v = W3[f * OUT_DIM + o];
        }
        g_b12[k] = sb;
        g_W3p[k] = w3v;
    }
}

// compute one stage (4 features) for both rows of this thread
static __device__ __forceinline__ void compute_stage(
    const float* __restrict__ sY, const float* __restrict__ sW,
    const float* __restrict__ sB, const float* __restrict__ sC,
    int tid, int s,
    unsigned long long& accA0, unsigned long long& accB0,
    unsigned long long& accA1, unsigned long long& accB1) {

    // vector y loads: 5 conflict-free LDS.128 per row
    const float4* yb0 = (const float4*)(sY + tid * YSTRIDE);
    const float4* yb1 = (const float4*)(sY + (tid + TPB) * YSTRIDE);
    float r0f[YCOLS], r1f[YCOLS];
    #pragma unroll
    for (int j = 0; j < 5; ++j) {
        *(float4*)&r0f[j * 4] = yb0[j];
        *(float4*)&r1f[j * 4] = yb1[j];
    }

    #pragma unroll
    for (int ff = 0; ff < FSUB; ++ff) {
        const int f = s * FSUB + ff;
        unsigned long long yp0[D_IN], yp1[D_IN];
        #pragma unroll
        for (int i = 0; i < D_IN; ++i) {
            const float v0 = r0f[ff * D_IN + i];
            const float v1 = r1f[ff * D_IN + i];
            yp0[i] = pk2(v0, v0);
            yp1[i] = pk2(v1, v1);
        }
        const ulonglong2* wp = (const ulonglong2*)(sW + f * D_IN * OPAD);
        const ulonglong2* bp = (const ulonglong2*)(sB + f * OPAD);
        const ulonglong2* cp = (const ulonglong2*)(sC + f * OPAD);

        #pragma unroll
        for (int j = 0; j < OPAD / 4; ++j) {
            ulonglong2 bb = bp[j];
            ulonglong2 t0 = bb, t1 = bb;
            #pragma unroll
            for (int i = 0; i < D_IN; ++i) {
                ulonglong2 w = wp[i * (OPAD / 4) + j];   // broadcast LDS.128
                t0.x = ffma2(yp0[i], w.x, t0.x);
                t0.y = ffma2(yp0[i], w.y, t0.y);
                t1.x = ffma2(yp1[i], w.x, t1.x);
                t1.y = ffma2(yp1[i], w.y, t1.y);
            }
            ulonglong2 c = cp[j];
            accA0 = ffma2(relu2(t0.x), c.x, accA0);
            accB0 = ffma2(relu2(t0.y), c.y, accB0);
            accA1 = ffma2(relu2(t1.x), c.x, accA1);
            accB1 = ffma2(relu2(t1.y), c.y, accB1);
        }
    }
}

// ---- Kernel 2: main fused MLP. Single reused y buffer -> 27.6KB smem, 6 CTAs/SM ----
__global__ __launch_bounds__(TPB, 6) void main_kernel(const float* __restrict__ y,
                                                      float* __restrict__ out,
                                                      const float* __restrict__ b3) {
    __shared__ __align__(16) float sW[FCHUNK * D_IN * OPAD];   // 1280 f
    __shared__ __align__(16) float sB[FCHUNK * OPAD];          // 256 f
    __shared__ __align__(16) float sC[FCHUNK * OPAD];          // 256 f
    __shared__ __align__(16) float sY[YTILE];                  // 5120 f (reused)
    __shared__ int s_ticket;

    const int tid  = threadIdx.x;
    const int fsplit = blockIdx.y;
    const int fbase = fsplit * FCHUNK;
    const int bx = blockIdx.x;
    const int b0 = bx * ROWS_PER_CTA;

    const unsigned sY_u32 = (unsigned)__cvta_generic_to_shared(sY);
    const float* ybase = y + (size_t)b0 * YROW + fbase * D_IN;

    // prologue: stage sub-tile 0, then weights
    stage_tile(sY_u32, ybase, tid);
    asm volatile("cp.async.commit_group;");

    {
        const float4* gw = (const float4*)(g_W12 + fbase * D_IN * OPAD);
        float4* sw4 = (float4*)sW;
        #pragma unroll
        for (int t = tid; t < FCHUNK * D_IN * OPAD / 4; t += TPB) sw4[t] = gw[t];
        if (tid < FCHUNK * OPAD / 4) {
            ((float4*)sB)[tid] = ((const float4*)(g_b12 + fbase * OPAD))[tid];
            ((float4*)sC)[tid] = ((const float4*)(g_W3p + fbase * OPAD))[tid];
        }
    }

    unsigned long long accA0 = 0ull, accB0 = 0ull;   // row b0+tid
    unsigned long long accA1 = 0ull, accB1 = 0ull;   // row b0+tid+TPB

    asm volatile("cp.async.wait_group 0;");
    __syncthreads();
    compute_stage(sY, sW, sB, sC, tid, 0, accA0, accB0, accA1, accB1);

    __syncthreads();                      // everyone done reading buffer
    stage_tile(sY_u32, ybase + FSUB * D_IN, tid);   // re-stage into SAME buffer
    asm volatile("cp.async.commit_group;");
    asm volatile("cp.async.wait_group 0;");
    __syncthreads();
    compute_stage(sY, sW, sB, sC, tid, 1, accA0, accB0, accA1, accB1);

    {
        float r0, r1, r2, r3;
        upk2(accA0, r0, r1); upk2(accB0, r2, r3);
        g_partial[fsplit][b0 + tid] = (r0 + r1) + (r2 + r3);
        upk2(accA1, r0, r1); upk2(accB1, r2, r3);
        g_partial[fsplit][b0 + tid + TPB] = (r0 + r1) + (r2 + r3);
    }

    // ---- fused deterministic reduction: last CTA of this bx sums all partials ----
    __threadfence();                 // publish our partial stores
    __syncthreads();                 // all threads of this CTA have stored+fenced
    if (tid == 0) s_ticket = atomicAdd(&g_count[bx], 1);
    __syncthreads();
    if (s_ticket == FSPLIT - 1) {
        __threadfence();             // acquire: see all other CTAs' partials
        const float bias3 = b3[0];
        #pragma unroll
        for (int rr = 0; rr < 2; ++rr) {
            const int row = b0 + tid + rr * TPB;
            float s0 = 0.f, s1 = 0.f, s2 = 0.f, s3 = 0.f, s4 = 0.f;
            #pragma unroll
            for (int p = 0; p < 5; ++p) {       // fixed order -> deterministic
                s0 += g_partial[p][row];
                s1 += g_partial[5 + p][row];
                s2 += g_partial[10 + p][row];
                s3 += g_partial[15 + p][row];
                s4 += g_partial[20 + p][row];
            }
            out[row] = (((s0 + s1) + (s2 + s3)) + s4) + bias3;
        }
    }
}

extern "C" void kernel_launch(void* const* d_in, const int* in_sizes, int n_in,
                              void* d_out, int out_size) {
    const float* y  = (const float*)d_in[0];
    const float* W1 = (const float*)d_in[1];
    const float* b1 = (const float*)d_in[2];
    const float* W2 = (const float*)d_in[3];
    const float* b2 = (const float*)d_in[4];
    const float* W3 = (const float*)d_in[5];
    const float* b3 = (const float*)d_in[6];
    float* out = (float*)d_out;

    {   // launch #1: fold weights + reset arrival counters
        const int total = F_TOTAL * D_IN * OPAD + F_TOTAL * OPAD;
        prep_kernel<<<(total + 255) / 256, 256>>>(W1, b1, W2, b2, W3);
    }

    // launch #2: main + fused reduce
    dim3 grid(NBX, FSPLIT);                      // 128 x 25 = 3200 CTAs
    main_kernel<<<grid, TPB>>>(y, out, b3);
}